// round 1
// baseline (speedup 1.0000x reference)
#include <cuda_runtime.h>
#include <cuda_fp16.h>
#include <cuda_bf16.h>
#include <cstdint>

// Problem constants
#define BB 4
#define TT 256
#define UU 128
#define D_ENC 512
#define D_PRED 640
#define HH 512
#define VV 1024
#define EPSV 1e-5f

// Scratch (device globals -- no allocation allowed)
__device__ float  g_enc [BB * TT * HH];    // (B*T, H) fp32 enc projection
__device__ float  g_pred[BB * UU * HH];    // (B*U, H) fp32 pred projection
__device__ __half g_woutT[HH * VV];        // W_out transposed: [k][n], fp16

// ---------------------------------------------------------------------------
// Small fp32 projection GEMM: C[M][N] = X[M][K] @ W[N][K]^T + bias[N]
// BM=BN=64, BK=16, 256 threads, 4x4 microtile
// ---------------------------------------------------------------------------
__global__ void proj_kernel(const float* __restrict__ X,
                            const float* __restrict__ W,
                            const float* __restrict__ bias,
                            float* __restrict__ C,
                            int M, int N, int K)
{
    __shared__ float Xs[16][65];
    __shared__ float Ws[16][65];
    const int m0 = blockIdx.y * 64;
    const int n0 = blockIdx.x * 64;
    const int tid = threadIdx.x;
    const int ty = tid >> 4, tx = tid & 15;

    float acc[4][4];
    #pragma unroll
    for (int i = 0; i < 4; i++)
        #pragma unroll
        for (int j = 0; j < 4; j++) acc[i][j] = 0.f;

    for (int k0 = 0; k0 < K; k0 += 16) {
        #pragma unroll
        for (int i = tid; i < 1024; i += 256) {
            int r = i >> 4, c = i & 15;
            Xs[c][r] = X[(size_t)(m0 + r) * K + k0 + c];
            Ws[c][r] = W[(size_t)(n0 + r) * K + k0 + c];
        }
        __syncthreads();
        #pragma unroll
        for (int kk = 0; kk < 16; kk++) {
            float a[4], b[4];
            #pragma unroll
            for (int i = 0; i < 4; i++) a[i] = Xs[kk][ty * 4 + i];
            #pragma unroll
            for (int j = 0; j < 4; j++) b[j] = Ws[kk][tx * 4 + j];
            #pragma unroll
            for (int i = 0; i < 4; i++)
                #pragma unroll
                for (int j = 0; j < 4; j++) acc[i][j] = fmaf(a[i], b[j], acc[i][j]);
        }
        __syncthreads();
    }
    #pragma unroll
    for (int i = 0; i < 4; i++)
        #pragma unroll
        for (int j = 0; j < 4; j++) {
            int m = m0 + ty * 4 + i, n = n0 + tx * 4 + j;
            C[(size_t)m * N + n] = acc[i][j] + bias[n];
        }
}

// ---------------------------------------------------------------------------
// W_out (V,H) fp32 -> g_woutT (H,V) fp16 transpose+convert
// ---------------------------------------------------------------------------
__global__ void wout_transpose_kernel(const float* __restrict__ W)
{
    int idx = blockIdx.x * blockDim.x + threadIdx.x;  // idx = k*1024 + n
    if (idx >= HH * VV) return;
    int k = idx >> 10;
    int n = idx & 1023;
    g_woutT[idx] = __float2half(W[(size_t)n * HH + k]);
}

// ---------------------------------------------------------------------------
// Fused joint kernel: per (b,t) block builds A = LN(relu(enc+pred)) (128x512
// fp16 in smem), then GEMM vs W_out^T (fp16, cp.async double-buffered) with
// mma.sync.m16n8k16, fused b_out bias epilogue.
// ---------------------------------------------------------------------------
#define AS_STRIDE 520                   // halves (1040B rows: 16B aligned, conflict-free ldmatrix)
#define BS_STRIDE 136                   // halves (272B rows)
#define A_BYTES   (128 * AS_STRIDE * 2) // 133120
#define BS_BUF_BYTES (32 * BS_STRIDE * 2) // 8704
#define B_BYTES   (2 * BS_BUF_BYTES)    // 17408
#define SMEM_BYTES (A_BYTES + B_BYTES + 3 * 512 * 4)  // 156672

__device__ __forceinline__ uint32_t smem_u32(const void* p) {
    return (uint32_t)__cvta_generic_to_shared(p);
}
__device__ __forceinline__ void ldmA(uint32_t a[4], uint32_t addr) {
    asm volatile("ldmatrix.sync.aligned.m8n8.x4.shared.b16 {%0,%1,%2,%3}, [%4];"
                 : "=r"(a[0]), "=r"(a[1]), "=r"(a[2]), "=r"(a[3]) : "r"(addr));
}
__device__ __forceinline__ void ldmBT(uint32_t b[4], uint32_t addr) {
    asm volatile("ldmatrix.sync.aligned.m8n8.x4.trans.shared.b16 {%0,%1,%2,%3}, [%4];"
                 : "=r"(b[0]), "=r"(b[1]), "=r"(b[2]), "=r"(b[3]) : "r"(addr));
}
__device__ __forceinline__ void mma16816(float c[4], const uint32_t a[4],
                                         uint32_t b0, uint32_t b1) {
    asm volatile(
        "mma.sync.aligned.m16n8k16.row.col.f32.f16.f16.f32 "
        "{%0,%1,%2,%3}, {%4,%5,%6,%7}, {%8,%9}, {%0,%1,%2,%3};"
        : "+f"(c[0]), "+f"(c[1]), "+f"(c[2]), "+f"(c[3])
        : "r"(a[0]), "r"(a[1]), "r"(a[2]), "r"(a[3]), "r"(b0), "r"(b1));
}
__device__ __forceinline__ void cp16(uint32_t dst, const void* src) {
    asm volatile("cp.async.cg.shared.global [%0], [%1], 16;" :: "r"(dst), "l"(src));
}

__global__ void __launch_bounds__(256, 1)
joint_kernel(const float* __restrict__ gamma, const float* __restrict__ beta,
             const float* __restrict__ b_out, float* __restrict__ out)
{
    extern __shared__ char smem[];
    __half* As = (__half*)smem;                          // [128][AS_STRIDE]
    __half* Bs = (__half*)(smem + A_BYTES);              // 2 x [32][BS_STRIDE]
    float*  encS   = (float*)(smem + A_BYTES + B_BYTES); // [512]
    float*  gammaS = encS + 512;
    float*  betaS  = gammaS + 512;

    const int bt  = blockIdx.x;
    const int bb  = bt >> 8;     // T = 256
    const int tid = threadIdx.x;

    for (int i = tid; i < 512; i += 256) {
        encS[i]   = g_enc[(size_t)bt * HH + i];
        gammaS[i] = gamma[i];
        betaS[i]  = beta[i];
    }
    __syncthreads();

    const int w = tid >> 5, lane = tid & 31;

    // ---- Phase 1: build A tile (ReLU + LayerNorm, fp32 math, fp16 store) ----
    for (int r = 0; r < 16; r++) {
        int u = w + r * 8;
        const float* pr = g_pred + ((size_t)(bb * UU + u)) * HH;
        float v[16];
        float s = 0.f, s2 = 0.f;
        #pragma unroll
        for (int i = 0; i < 16; i++) {
            int h = lane + (i << 5);
            float x = encS[h] + pr[h];
            x = fmaxf(x, 0.f);
            v[i] = x; s += x; s2 += x * x;
        }
        #pragma unroll
        for (int o = 16; o; o >>= 1) {
            s  += __shfl_xor_sync(0xffffffffu, s,  o);
            s2 += __shfl_xor_sync(0xffffffffu, s2, o);
        }
        float mean = s * (1.f / 512.f);
        float var  = fmaxf(s2 * (1.f / 512.f) - mean * mean, 0.f);
        float rstd = rsqrtf(var + EPSV);
        #pragma unroll
        for (int i = 0; i < 16; i++) {
            int h = lane + (i << 5);
            As[u * AS_STRIDE + h] =
                __float2half((v[i] - mean) * rstd * gammaS[h] + betaS[h]);
        }
    }
    __syncthreads();

    // ---- Phase 2: GEMM 128x1024x512 ----
    const int warpM = w & 3;    // 4 M-groups of 32 rows
    const int warpN = w >> 2;   // 2 N-groups of 64 cols
    const uint32_t As_u = smem_u32(As);
    const uint32_t Bs_u = smem_u32(Bs);

    // per-lane ldmatrix base addresses
    const uint32_t aLane =
        As_u + (uint32_t)(((warpM * 32 + (lane & 15)) * AS_STRIDE + ((lane >> 4) << 3)) * 2);
    const uint32_t bLane0 =
        (uint32_t)(((lane & 15) * BS_STRIDE + warpN * 64 + ((lane >> 4) << 3)) * 2);

    float acc[2][8][4];
    const size_t outBase = (size_t)bt * (UU * VV);

    for (int no = 0; no < 8; no++) {
        const int n0 = no << 7;
        #pragma unroll
        for (int mi = 0; mi < 2; mi++)
            #pragma unroll
            for (int ni = 0; ni < 8; ni++)
                #pragma unroll
                for (int q = 0; q < 4; q++) acc[mi][ni][q] = 0.f;

        // preload k-chunk 0 into buf 0
        {
            #pragma unroll
            for (int p = 0; p < 2; p++) {
                int idx = tid + (p << 8);
                int kr = idx >> 4, seg = idx & 15;
                const __half* src = g_woutT + (size_t)kr * VV + n0 + (seg << 3);
                cp16(Bs_u + (uint32_t)((kr * BS_STRIDE + (seg << 3)) * 2), src);
            }
            asm volatile("cp.async.commit_group;");
            asm volatile("cp.async.wait_group 0;" ::: "memory");
            __syncthreads();
        }

        for (int kc = 0; kc < 16; kc++) {
            const int buf = kc & 1;
            if (kc < 15) {   // prefetch next chunk into other buffer
                const int kn = (kc + 1) << 5;
                const uint32_t dstBase = Bs_u + (uint32_t)((buf ^ 1) * BS_BUF_BYTES);
                #pragma unroll
                for (int p = 0; p < 2; p++) {
                    int idx = tid + (p << 8);
                    int kr = idx >> 4, seg = idx & 15;
                    const __half* src = g_woutT + (size_t)(kn + kr) * VV + n0 + (seg << 3);
                    cp16(dstBase + (uint32_t)((kr * BS_STRIDE + (seg << 3)) * 2), src);
                }
                asm volatile("cp.async.commit_group;");
            }
            const int kglob = kc << 5;
            const uint32_t bufBase = Bs_u + (uint32_t)(buf * BS_BUF_BYTES);
            #pragma unroll
            for (int kk = 0; kk < 32; kk += 16) {
                uint32_t a[2][4];
                ldmA(a[0], aLane + (uint32_t)((kglob + kk) * 2));
                ldmA(a[1], aLane + (uint32_t)((16 * AS_STRIDE + kglob + kk) * 2));
                uint32_t bf[4][4];
                #pragma unroll
                for (int j = 0; j < 4; j++)
                    ldmBT(bf[j], bufBase + bLane0 + (uint32_t)((kk * BS_STRIDE + j * 16) * 2));
                #pragma unroll
                for (int mi = 0; mi < 2; mi++)
                    #pragma unroll
                    for (int ni = 0; ni < 8; ni++)
                        mma16816(acc[mi][ni], a[mi],
                                 bf[ni >> 1][(ni & 1) * 2],
                                 bf[ni >> 1][(ni & 1) * 2 + 1]);
            }
            asm volatile("cp.async.wait_group 0;" ::: "memory");
            __syncthreads();
        }

        // epilogue: add b_out, write fp32
        #pragma unroll
        for (int mi = 0; mi < 2; mi++) {
            const int row = warpM * 32 + mi * 16 + (lane >> 2);
            #pragma unroll
            for (int ni = 0; ni < 8; ni++) {
                const int col = n0 + warpN * 64 + ni * 8 + ((lane & 3) << 1);
                const float2 bo = *reinterpret_cast<const float2*>(b_out + col);
                float2 v0 = make_float2(acc[mi][ni][0] + bo.x, acc[mi][ni][1] + bo.y);
                float2 v1 = make_float2(acc[mi][ni][2] + bo.x, acc[mi][ni][3] + bo.y);
                *reinterpret_cast<float2*>(out + outBase + (size_t)row * VV + col)       = v0;
                *reinterpret_cast<float2*>(out + outBase + (size_t)(row + 8) * VV + col) = v1;
            }
        }
    }
}

// ---------------------------------------------------------------------------
extern "C" void kernel_launch(void* const* d_in, const int* in_sizes, int n_in,
                              void* d_out, int out_size)
{
    (void)in_sizes; (void)n_in; (void)out_size;
    const float* enc_in  = (const float*)d_in[0];
    const float* pred_in = (const float*)d_in[1];
    const float* W_enc   = (const float*)d_in[2];
    const float* b_enc   = (const float*)d_in[3];
    const float* W_pred  = (const float*)d_in[4];
    const float* b_pred  = (const float*)d_in[5];
    const float* gamma   = (const float*)d_in[6];
    const float* beta    = (const float*)d_in[7];
    const float* W_out   = (const float*)d_in[8];
    const float* b_out   = (const float*)d_in[9];
    float* out = (float*)d_out;

    float* enc_ptr = nullptr;
    float* pred_ptr = nullptr;
    cudaGetSymbolAddress((void**)&enc_ptr,  g_enc);
    cudaGetSymbolAddress((void**)&pred_ptr, g_pred);

    // prep kernels
    wout_transpose_kernel<<<(HH * VV + 255) / 256, 256>>>(W_out);
    proj_kernel<<<dim3(HH / 64, (BB * TT) / 64), 256>>>(enc_in,  W_enc,  b_enc,  enc_ptr,
                                                        BB * TT, HH, D_ENC);
    proj_kernel<<<dim3(HH / 64, (BB * UU) / 64), 256>>>(pred_in, W_pred, b_pred, pred_ptr,
                                                        BB * UU, HH, D_PRED);

    // fused joint
    cudaFuncSetAttribute(joint_kernel, cudaFuncAttributeMaxDynamicSharedMemorySize,
                         SMEM_BYTES);
    joint_kernel<<<BB * TT, 256, SMEM_BYTES>>>(gamma, beta, b_out, out);
}

// round 3
// speedup vs baseline: 1.2581x; 1.2581x over previous
#include <cuda_runtime.h>
#include <cuda_fp16.h>
#include <cuda_bf16.h>
#include <cstdint>

#define BB 4
#define TT 256
#define UU 128
#define D_ENC 512
#define D_PRED 640
#define HH 512
#define VV 1024
#define EPSV 1e-5f

// Device scratch
__device__ float  g_enc [BB * TT * HH];
__device__ float  g_pred[BB * UU * HH];
__device__ __half g_wout[VV * HH];      // fp16 copy of W_out, [v][h]

// ---------------------------------------------------------------------------
// fp32 projection GEMM: C[M][N] = X[M][K] @ W[N][K]^T + bias[N]
// ---------------------------------------------------------------------------
__global__ void proj_kernel(const float* __restrict__ X,
                            const float* __restrict__ W,
                            const float* __restrict__ bias,
                            float* __restrict__ C,
                            int M, int N, int K)
{
    __shared__ float Xs[16][65];
    __shared__ float Ws[16][65];
    const int m0 = blockIdx.y * 64;
    const int n0 = blockIdx.x * 64;
    const int tid = threadIdx.x;
    const int ty = tid >> 4, tx = tid & 15;

    float acc[4][4];
    #pragma unroll
    for (int i = 0; i < 4; i++)
        #pragma unroll
        for (int j = 0; j < 4; j++) acc[i][j] = 0.f;

    for (int k0 = 0; k0 < K; k0 += 16) {
        #pragma unroll
        for (int i = tid; i < 1024; i += 256) {
            int r = i >> 4, c = i & 15;
            Xs[c][r] = X[(size_t)(m0 + r) * K + k0 + c];
            Ws[c][r] = W[(size_t)(n0 + r) * K + k0 + c];
        }
        __syncthreads();
        #pragma unroll
        for (int kk = 0; kk < 16; kk++) {
            float a[4], b[4];
            #pragma unroll
            for (int i = 0; i < 4; i++) a[i] = Xs[kk][ty * 4 + i];
            #pragma unroll
            for (int j = 0; j < 4; j++) b[j] = Ws[kk][tx * 4 + j];
            #pragma unroll
            for (int i = 0; i < 4; i++)
                #pragma unroll
                for (int j = 0; j < 4; j++) acc[i][j] = fmaf(a[i], b[j], acc[i][j]);
        }
        __syncthreads();
    }
    #pragma unroll
    for (int i = 0; i < 4; i++)
        #pragma unroll
        for (int j = 0; j < 4; j++) {
            int m = m0 + ty * 4 + i, n = n0 + tx * 4 + j;
            C[(size_t)m * N + n] = acc[i][j] + bias[n];
        }
}

__global__ void wout_convert_kernel(const float* __restrict__ W)
{
    int idx = blockIdx.x * blockDim.x + threadIdx.x;
    if (idx < VV * HH) g_wout[idx] = __float2half(W[idx]);
}

// ---------------------------------------------------------------------------
// mma.sync helpers
// ---------------------------------------------------------------------------
__device__ __forceinline__ uint32_t smem_u32(const void* p) {
    return (uint32_t)__cvta_generic_to_shared(p);
}
__device__ __forceinline__ void ldmX4(uint32_t a[4], uint32_t addr) {
    asm volatile("ldmatrix.sync.aligned.m8n8.x4.shared.b16 {%0,%1,%2,%3}, [%4];"
                 : "=r"(a[0]), "=r"(a[1]), "=r"(a[2]), "=r"(a[3]) : "r"(addr));
}
__device__ __forceinline__ void mma16816(float c[4], const uint32_t a[4],
                                         uint32_t b0, uint32_t b1) {
    asm volatile(
        "mma.sync.aligned.m16n8k16.row.col.f32.f16.f16.f32 "
        "{%0,%1,%2,%3}, {%4,%5,%6,%7}, {%8,%9}, {%0,%1,%2,%3};"
        : "+f"(c[0]), "+f"(c[1]), "+f"(c[2]), "+f"(c[3])
        : "r"(a[0]), "r"(a[1]), "r"(a[2]), "r"(a[3]), "r"(b0), "r"(b1));
}
__device__ __forceinline__ void cp16(uint32_t dst, const void* src) {
    asm volatile("cp.async.cg.shared.global [%0], [%1], 16;" :: "r"(dst), "l"(src));
}

// ---------------------------------------------------------------------------
// joint kernel: 512 threads, BM=128 (all of U), BN=256 chunk, BK=32 chunks
// A: LN(relu(enc+pred)) fp16 in smem [128][520]
// B: g_wout rows [n][k], smem rows padded to 80B, non-trans ldmatrix
// ---------------------------------------------------------------------------
#define AS_STRIDE 520                         // halves
#define A_BYTES   (128 * AS_STRIDE * 2)       // 133120
#define BS_ROWB   80                          // bytes per n-row (64B data + 16B pad)
#define B_CHUNK   (256 * BS_ROWB)             // 20480
#define OFF_A     0
#define OFF_B     133120
#define OFF_BIAS  (OFF_B + 2 * B_CHUNK)       // 174080
#define OFF_ENC   (OFF_BIAS + 4096)
#define OFF_GAM   (OFF_ENC + 2048)
#define OFF_BET   (OFF_GAM + 2048)
#define SMEM_TOTAL (OFF_BET + 2048)           // 184320

__global__ void __launch_bounds__(512, 1)
joint_kernel(const float* __restrict__ gamma, const float* __restrict__ beta,
             const float* __restrict__ b_out, float* __restrict__ out)
{
    extern __shared__ __align__(1024) char smem[];
    const uint32_t smemU = smem_u32(smem);

    const int bt  = blockIdx.x;
    const int bb  = bt >> 8;
    const int tid = threadIdx.x;
    const int w   = tid >> 5, lane = tid & 31;

    __half* As    = (__half*)(smem + OFF_A);
    float* biasS  = (float*)(smem + OFF_BIAS);
    float* encS   = (float*)(smem + OFF_ENC);
    float* gammaS = (float*)(smem + OFF_GAM);
    float* betaS  = (float*)(smem + OFF_BET);

    for (int i = tid; i < 512; i += 512) {
        encS[i]   = g_enc[(size_t)bt * HH + i];
        gammaS[i] = gamma[i];
        betaS[i]  = beta[i];
    }
    for (int i = tid; i < 1024; i += 512) biasS[i] = b_out[i];
    __syncthreads();

    // ---- Phase 1: A = LN(relu(enc+pred)) fp16 ----
    #pragma unroll
    for (int r = 0; r < 8; r++) {
        const int u = r * 16 + w;
        const float* pr = g_pred + ((size_t)(bb * UU + u)) * HH;
        float v[16];
        float s = 0.f, s2 = 0.f;
        #pragma unroll
        for (int i = 0; i < 16; i++) {
            int h = lane + (i << 5);
            float x = encS[h] + pr[h];
            x = fmaxf(x, 0.f);
            v[i] = x; s += x; s2 += x * x;
        }
        #pragma unroll
        for (int o = 16; o; o >>= 1) {
            s  += __shfl_xor_sync(0xffffffffu, s,  o);
            s2 += __shfl_xor_sync(0xffffffffu, s2, o);
        }
        float mean = s * (1.f / 512.f);
        float var  = fmaxf(s2 * (1.f / 512.f) - mean * mean, 0.f);
        float rstd = rsqrtf(var + EPSV);
        #pragma unroll
        for (int i = 0; i < 16; i++) {
            int h = lane + (i << 5);
            As[u * AS_STRIDE + h] =
                __float2half((v[i] - mean) * rstd * gammaS[h] + betaS[h]);
        }
    }
    __syncthreads();

    // ---- Phase 2: GEMM 128x1024x512 ----
    const int warpM = w & 3;     // 4 M-groups of 32 rows
    const int warpN = w >> 2;    // 4 N-groups of 64 cols (within BN=256)
    const uint32_t As_u = smemU + OFF_A;
    const uint32_t Bs_u = smemU + OFF_B;

    // A ldmatrix lane address (row-major A, x4 -> m16k16 frag pair layout)
    const uint32_t aLane =
        As_u + (uint32_t)(((warpM * 32 + (lane & 15)) * AS_STRIDE + ((lane >> 4) << 3)) * 2);
    // B ldmatrix lane address: non-trans over n-rows
    // lanes 0-7: n 0-7 @k lo | 8-15: n 0-7 @k hi | 16-23: n 8-15 @k lo | 24-31: n 8-15 @k hi
    const int nLaneRow = (lane & 7) + ((lane >> 4) << 3);
    const int kLaneOff = ((lane >> 3) & 1) << 3;   // 0 or 8 halves
    const uint32_t bLane =
        (uint32_t)((warpN * 64 + nLaneRow) * BS_ROWB + kLaneOff * 2);

    float acc[2][8][4];
    const size_t outBase = (size_t)bt * (UU * VV);

    for (int no = 0; no < 4; no++) {
        const int n0 = no << 8;
        #pragma unroll
        for (int mi = 0; mi < 2; mi++)
            #pragma unroll
            for (int ni = 0; ni < 8; ni++)
                #pragma unroll
                for (int q = 0; q < 4; q++) acc[mi][ni][q] = 0.f;

        // preload k-chunk 0 into buf 0: 256 rows x 64B, 4 segs/row, 2 per thread
        {
            #pragma unroll
            for (int p = 0; p < 2; p++) {
                int idx = tid + (p << 9);
                int nr = idx >> 2, seg = idx & 3;
                cp16(Bs_u + (uint32_t)(nr * BS_ROWB + seg * 16),
                     g_wout + (size_t)(n0 + nr) * HH + (seg << 3));
            }
            asm volatile("cp.async.commit_group;");
            asm volatile("cp.async.wait_group 0;" ::: "memory");
            __syncthreads();
        }

        for (int kc = 0; kc < 16; kc++) {
            const int buf = kc & 1;
            if (kc < 15) {
                const int kn = (kc + 1) << 5;
                const uint32_t dstBase = Bs_u + (uint32_t)((buf ^ 1) * B_CHUNK);
                #pragma unroll
                for (int p = 0; p < 2; p++) {
                    int idx = tid + (p << 9);
                    int nr = idx >> 2, seg = idx & 3;
                    cp16(dstBase + (uint32_t)(nr * BS_ROWB + seg * 16),
                         g_wout + (size_t)(n0 + nr) * HH + kn + (seg << 3));
                }
                asm volatile("cp.async.commit_group;");
            }
            const int kglob = kc << 5;
            const uint32_t bufB = Bs_u + (uint32_t)(buf * B_CHUNK) + bLane;
            #pragma unroll
            for (int kk = 0; kk < 32; kk += 16) {
                uint32_t a[2][4];
                ldmX4(a[0], aLane + (uint32_t)((kglob + kk) * 2));
                ldmX4(a[1], aLane + (uint32_t)((16 * AS_STRIDE + kglob + kk) * 2));
                uint32_t bf[4][4];
                #pragma unroll
                for (int j = 0; j < 4; j++)
                    ldmX4(bf[j], bufB + (uint32_t)((j * 16) * BS_ROWB + kk * 2));
                #pragma unroll
                for (int mi = 0; mi < 2; mi++)
                    #pragma unroll
                    for (int ni = 0; ni < 8; ni++)
                        mma16816(acc[mi][ni], a[mi],
                                 bf[ni >> 1][(ni & 1) * 2],
                                 bf[ni >> 1][(ni & 1) * 2 + 1]);
            }
            asm volatile("cp.async.wait_group 0;" ::: "memory");
            __syncthreads();
        }

        // epilogue
        #pragma unroll
        for (int mi = 0; mi < 2; mi++) {
            const int row = warpM * 32 + mi * 16 + (lane >> 2);
            #pragma unroll
            for (int ni = 0; ni < 8; ni++) {
                const int col = n0 + warpN * 64 + ni * 8 + ((lane & 3) << 1);
                const float2 bo = *reinterpret_cast<const float2*>(biasS + col);
                float2 v0 = make_float2(acc[mi][ni][0] + bo.x, acc[mi][ni][1] + bo.y);
                float2 v1 = make_float2(acc[mi][ni][2] + bo.x, acc[mi][ni][3] + bo.y);
                *reinterpret_cast<float2*>(out + outBase + (size_t)row * VV + col)       = v0;
                *reinterpret_cast<float2*>(out + outBase + (size_t)(row + 8) * VV + col) = v1;
            }
        }
    }
}

// ---------------------------------------------------------------------------
extern "C" void kernel_launch(void* const* d_in, const int* in_sizes, int n_in,
                              void* d_out, int out_size)
{
    (void)in_sizes; (void)n_in; (void)out_size;
    const float* enc_in  = (const float*)d_in[0];
    const float* pred_in = (const float*)d_in[1];
    const float* W_enc   = (const float*)d_in[2];
    const float* b_enc   = (const float*)d_in[3];
    const float* W_pred  = (const float*)d_in[4];
    const float* b_pred  = (const float*)d_in[5];
    const float* gamma   = (const float*)d_in[6];
    const float* beta    = (const float*)d_in[7];
    const float* W_out   = (const float*)d_in[8];
    const float* b_out   = (const float*)d_in[9];
    float* out = (float*)d_out;

    float* enc_ptr = nullptr;
    float* pred_ptr = nullptr;
    cudaGetSymbolAddress((void**)&enc_ptr,  g_enc);
    cudaGetSymbolAddress((void**)&pred_ptr, g_pred);

    wout_convert_kernel<<<(VV * HH + 255) / 256, 256>>>(W_out);
    proj_kernel<<<dim3(HH / 64, (BB * TT) / 64), 256>>>(enc_in,  W_enc,  b_enc,  enc_ptr,
                                                        BB * TT, HH, D_ENC);
    proj_kernel<<<dim3(HH / 64, (BB * UU) / 64), 256>>>(pred_in, W_pred, b_pred, pred_ptr,
                                                        BB * UU, HH, D_PRED);

    cudaFuncSetAttribute(joint_kernel, cudaFuncAttributeMaxDynamicSharedMemorySize,
                         SMEM_TOTAL);
    joint_kernel<<<BB * TT, 512, SMEM_TOTAL>>>(gamma, beta, b_out, out);
}

// round 4
// speedup vs baseline: 1.4561x; 1.1574x over previous
#include <cuda_runtime.h>
#include <cuda_fp16.h>
#include <cuda_bf16.h>
#include <cstdint>

#define BB 4
#define TT 256
#define UU 128
#define D_ENC 512
#define D_PRED 640
#define HH 512
#define VV 1024
#define EPSV 1e-5f

// Device scratch
__device__ float  g_enc [BB * TT * HH];
__device__ float  g_pred[BB * UU * HH];
__device__ __half g_wout[VV * HH];      // fp16 copy of W_out, [v][h]

// ---------------------------------------------------------------------------
// fp32 projection GEMM: C[M][N] = X[M][K] @ W[N][K]^T + bias[N]
// ---------------------------------------------------------------------------
__global__ void proj_kernel(const float* __restrict__ X,
                            const float* __restrict__ W,
                            const float* __restrict__ bias,
                            float* __restrict__ C,
                            int M, int N, int K)
{
    __shared__ float Xs[16][65];
    __shared__ float Ws[16][65];
    const int m0 = blockIdx.y * 64;
    const int n0 = blockIdx.x * 64;
    const int tid = threadIdx.x;
    const int ty = tid >> 4, tx = tid & 15;

    float acc[4][4];
    #pragma unroll
    for (int i = 0; i < 4; i++)
        #pragma unroll
        for (int j = 0; j < 4; j++) acc[i][j] = 0.f;

    for (int k0 = 0; k0 < K; k0 += 16) {
        #pragma unroll
        for (int i = tid; i < 1024; i += 256) {
            int r = i >> 4, c = i & 15;
            Xs[c][r] = X[(size_t)(m0 + r) * K + k0 + c];
            Ws[c][r] = W[(size_t)(n0 + r) * K + k0 + c];
        }
        __syncthreads();
        #pragma unroll
        for (int kk = 0; kk < 16; kk++) {
            float a[4], b[4];
            #pragma unroll
            for (int i = 0; i < 4; i++) a[i] = Xs[kk][ty * 4 + i];
            #pragma unroll
            for (int j = 0; j < 4; j++) b[j] = Ws[kk][tx * 4 + j];
            #pragma unroll
            for (int i = 0; i < 4; i++)
                #pragma unroll
                for (int j = 0; j < 4; j++) acc[i][j] = fmaf(a[i], b[j], acc[i][j]);
        }
        __syncthreads();
    }
    #pragma unroll
    for (int i = 0; i < 4; i++)
        #pragma unroll
        for (int j = 0; j < 4; j++) {
            int m = m0 + ty * 4 + i, n = n0 + tx * 4 + j;
            C[(size_t)m * N + n] = acc[i][j] + bias[n];
        }
}

__global__ void wout_convert_kernel(const float* __restrict__ W)
{
    int idx = blockIdx.x * blockDim.x + threadIdx.x;
    if (idx < VV * HH) g_wout[idx] = __float2half(W[idx]);
}

// ---------------------------------------------------------------------------
// mma.sync helpers
// ---------------------------------------------------------------------------
__device__ __forceinline__ uint32_t smem_u32(const void* p) {
    return (uint32_t)__cvta_generic_to_shared(p);
}
__device__ __forceinline__ void ldmX4(uint32_t a[4], uint32_t addr) {
    asm volatile("ldmatrix.sync.aligned.m8n8.x4.shared.b16 {%0,%1,%2,%3}, [%4];"
                 : "=r"(a[0]), "=r"(a[1]), "=r"(a[2]), "=r"(a[3]) : "r"(addr));
}
__device__ __forceinline__ void mma16816(float c[4], const uint32_t a[4],
                                         uint32_t b0, uint32_t b1) {
    asm volatile(
        "mma.sync.aligned.m16n8k16.row.col.f32.f16.f16.f32 "
        "{%0,%1,%2,%3}, {%4,%5,%6,%7}, {%8,%9}, {%0,%1,%2,%3};"
        : "+f"(c[0]), "+f"(c[1]), "+f"(c[2]), "+f"(c[3])
        : "r"(a[0]), "r"(a[1]), "r"(a[2]), "r"(a[3]), "r"(b0), "r"(b1));
}
__device__ __forceinline__ void cp16(uint32_t dst, const void* src) {
    asm volatile("cp.async.cg.shared.global [%0], [%1], 16;" :: "r"(dst), "l"(src));
}

// ---------------------------------------------------------------------------
// joint kernel: BM=64 (half of U) so 2 CTAs fit per SM. 256 threads.
// 8 warps = warpM(2: 32 rows) x warpN(4: 64 cols) over BN=256 chunks.
// A: LN(relu(enc+pred)) fp16 [64][520] padded rows.
// B: W_out n-rows, 64B/row XOR-swizzled (seg ^= (n>>1)&3), double buffered.
// ---------------------------------------------------------------------------
#define AS_STRIDE 520
#define A_BYTES   (64 * AS_STRIDE * 2)       // 66560
#define B_CHUNK   (256 * 64)                 // 16384
#define OFF_A     0
#define OFF_B     66560
#define OFF_BIAS  (OFF_B + 2 * B_CHUNK)      // 99328
#define OFF_ENC   (OFF_BIAS + 4096)          // 103424
#define OFF_GAM   (OFF_ENC + 2048)           // 105472
#define OFF_BET   (OFF_GAM + 2048)           // 107520
#define SMEM_TOTAL (OFF_BET + 2048)          // 109568

__global__ void __launch_bounds__(256, 2)
joint_kernel(const float* __restrict__ gamma, const float* __restrict__ beta,
             const float* __restrict__ b_out, float* __restrict__ out)
{
    extern __shared__ __align__(1024) char smem[];
    const uint32_t smemU = smem_u32(smem);

    const int bt   = blockIdx.x >> 1;
    const int half = blockIdx.x & 1;
    const int bb   = bt >> 8;
    const int tid  = threadIdx.x;
    const int w    = tid >> 5, lane = tid & 31;

    __half* As    = (__half*)(smem + OFF_A);
    float* biasS  = (float*)(smem + OFF_BIAS);
    float* encS   = (float*)(smem + OFF_ENC);
    float* gammaS = (float*)(smem + OFF_GAM);
    float* betaS  = (float*)(smem + OFF_BET);

    for (int i = tid; i < 512; i += 256) {
        encS[i]   = g_enc[(size_t)bt * HH + i];
        gammaS[i] = gamma[i];
        betaS[i]  = beta[i];
    }
    for (int i = tid; i < 1024; i += 256) biasS[i] = b_out[i];
    __syncthreads();

    // ---- Phase 1: A = LN(relu(enc+pred)) fp16, rows = half*64 .. +63 ----
    #pragma unroll
    for (int r = 0; r < 8; r++) {
        const int u = r * 8 + w;                       // local row 0..63
        const int ug = half * 64 + u;                  // global u
        const float* pr = g_pred + ((size_t)(bb * UU + ug)) * HH;
        float v[16];
        float s = 0.f, s2 = 0.f;
        #pragma unroll
        for (int i = 0; i < 16; i++) {
            int h = lane + (i << 5);
            float x = encS[h] + pr[h];
            x = fmaxf(x, 0.f);
            v[i] = x; s += x; s2 += x * x;
        }
        #pragma unroll
        for (int o = 16; o; o >>= 1) {
            s  += __shfl_xor_sync(0xffffffffu, s,  o);
            s2 += __shfl_xor_sync(0xffffffffu, s2, o);
        }
        float mean = s * (1.f / 512.f);
        float var  = fmaxf(s2 * (1.f / 512.f) - mean * mean, 0.f);
        float rstd = rsqrtf(var + EPSV);
        #pragma unroll
        for (int i = 0; i < 16; i++) {
            int h = lane + (i << 5);
            As[u * AS_STRIDE + h] =
                __float2half((v[i] - mean) * rstd * gammaS[h] + betaS[h]);
        }
    }
    __syncthreads();

    // ---- Phase 2: GEMM 64x1024x512 ----
    const int warpM = w & 1;     // 2 M-groups of 32 rows
    const int warpN = w >> 1;    // 4 N-groups of 64 cols
    const uint32_t As_u = smemU + OFF_A;
    const uint32_t Bs_u = smemU + OFF_B;

    const uint32_t aLane =
        As_u + (uint32_t)(((warpM * 32 + (lane & 15)) * AS_STRIDE + ((lane >> 4) << 3)) * 2);

    // B lane constants: n row within 64B swizzled rows
    const int nLaneRow = (lane & 7) + ((lane >> 4) << 3);     // 0..15 within tile
    const int khalf    = (lane >> 3) & 1;                     // 0/1 -> +16B
    uint32_t bBase[4], bXor[4];
    #pragma unroll
    for (int j = 0; j < 4; j++) {
        const int n = warpN * 64 + j * 16 + nLaneRow;
        bBase[j] = (uint32_t)(n * 64);
        bXor[j]  = (uint32_t)(((n >> 1) & 3) << 4);
    }

    float acc[2][8][4];
    const size_t outBase = (size_t)bt * (UU * VV) + (size_t)half * 64 * VV;

    for (int no = 0; no < 4; no++) {
        const int n0 = no << 8;
        #pragma unroll
        for (int mi = 0; mi < 2; mi++)
            #pragma unroll
            for (int ni = 0; ni < 8; ni++)
                #pragma unroll
                for (int q = 0; q < 4; q++) acc[mi][ni][q] = 0.f;

        // preload k-chunk 0 into buf 0: 256 rows x 64B (4 segs), 4 per thread
        {
            #pragma unroll
            for (int p = 0; p < 4; p++) {
                int idx = tid + (p << 8);
                int nr = idx >> 2, seg = idx & 3;
                uint32_t dst = (uint32_t)(nr * 64 + (((seg ^ ((nr >> 1) & 3))) << 4));
                cp16(Bs_u + dst, g_wout + (size_t)(n0 + nr) * HH + (seg << 3));
            }
            asm volatile("cp.async.commit_group;");
            asm volatile("cp.async.wait_group 0;" ::: "memory");
            __syncthreads();
        }

        for (int kc = 0; kc < 16; kc++) {
            const int buf = kc & 1;
            if (kc < 15) {
                const int kn = (kc + 1) << 5;
                const uint32_t dstBase = Bs_u + (uint32_t)((buf ^ 1) * B_CHUNK);
                #pragma unroll
                for (int p = 0; p < 4; p++) {
                    int idx = tid + (p << 8);
                    int nr = idx >> 2, seg = idx & 3;
                    uint32_t dst = (uint32_t)(nr * 64 + (((seg ^ ((nr >> 1) & 3))) << 4));
                    cp16(dstBase + dst, g_wout + (size_t)(n0 + nr) * HH + kn + (seg << 3));
                }
                asm volatile("cp.async.commit_group;");
            }
            const int kglob = kc << 5;
            const uint32_t bufB = Bs_u + (uint32_t)(buf * B_CHUNK);
            #pragma unroll
            for (int kk2 = 0; kk2 < 2; kk2++) {
                const int kk = kk2 << 4;
                uint32_t a[2][4];
                ldmX4(a[0], aLane + (uint32_t)((kglob + kk) * 2));
                ldmX4(a[1], aLane + (uint32_t)((16 * AS_STRIDE + kglob + kk) * 2));
                const uint32_t seg = (uint32_t)((kk2 << 1) + khalf) << 4;
                uint32_t bf[4][4];
                #pragma unroll
                for (int j = 0; j < 4; j++)
                    ldmX4(bf[j], bufB + bBase[j] + (seg ^ bXor[j]));
                #pragma unroll
                for (int mi = 0; mi < 2; mi++)
                    #pragma unroll
                    for (int ni = 0; ni < 8; ni++)
                        mma16816(acc[mi][ni], a[mi],
                                 bf[ni >> 1][(ni & 1) * 2],
                                 bf[ni >> 1][(ni & 1) * 2 + 1]);
            }
            asm volatile("cp.async.wait_group 0;" ::: "memory");
            __syncthreads();
        }

        // epilogue
        #pragma unroll
        for (int mi = 0; mi < 2; mi++) {
            const int row = warpM * 32 + mi * 16 + (lane >> 2);
            #pragma unroll
            for (int ni = 0; ni < 8; ni++) {
                const int col = n0 + warpN * 64 + ni * 8 + ((lane & 3) << 1);
                const float2 bo = *reinterpret_cast<const float2*>(biasS + col);
                float2 v0 = make_float2(acc[mi][ni][0] + bo.x, acc[mi][ni][1] + bo.y);
                float2 v1 = make_float2(acc[mi][ni][2] + bo.x, acc[mi][ni][3] + bo.y);
                *reinterpret_cast<float2*>(out + outBase + (size_t)row * VV + col)       = v0;
                *reinterpret_cast<float2*>(out + outBase + (size_t)(row + 8) * VV + col) = v1;
            }
        }
    }
}

// ---------------------------------------------------------------------------
extern "C" void kernel_launch(void* const* d_in, const int* in_sizes, int n_in,
                              void* d_out, int out_size)
{
    (void)in_sizes; (void)n_in; (void)out_size;
    const float* enc_in  = (const float*)d_in[0];
    const float* pred_in = (const float*)d_in[1];
    const float* W_enc   = (const float*)d_in[2];
    const float* b_enc   = (const float*)d_in[3];
    const float* W_pred  = (const float*)d_in[4];
    const float* b_pred  = (const float*)d_in[5];
    const float* gamma   = (const float*)d_in[6];
    const float* beta    = (const float*)d_in[7];
    const float* W_out   = (const float*)d_in[8];
    const float* b_out   = (const float*)d_in[9];
    float* out = (float*)d_out;

    float* enc_ptr = nullptr;
    float* pred_ptr = nullptr;
    cudaGetSymbolAddress((void**)&enc_ptr,  g_enc);
    cudaGetSymbolAddress((void**)&pred_ptr, g_pred);

    wout_convert_kernel<<<(VV * HH + 255) / 256, 256>>>(W_out);
    proj_kernel<<<dim3(HH / 64, (BB * TT) / 64), 256>>>(enc_in,  W_enc,  b_enc,  enc_ptr,
                                                        BB * TT, HH, D_ENC);
    proj_kernel<<<dim3(HH / 64, (BB * UU) / 64), 256>>>(pred_in, W_pred, b_pred, pred_ptr,
                                                        BB * UU, HH, D_PRED);

    cudaFuncSetAttribute(joint_kernel, cudaFuncAttributeMaxDynamicSharedMemorySize,
                         SMEM_TOTAL);
    joint_kernel<<<BB * TT * 2, 256, SMEM_TOTAL>>>(gamma, beta, b_out, out);
}

// round 5
// speedup vs baseline: 1.5186x; 1.0429x over previous
#include <cuda_runtime.h>
#include <cuda_fp16.h>
#include <cuda_bf16.h>
#include <cstdint>

#define BB 4
#define TT 256
#define UU 128
#define D_ENC 512
#define D_PRED 640
#define HH 512
#define VV 1024
#define EPSV 1e-5f

// Device scratch
__device__ float  g_enc [BB * TT * HH];
__device__ float  g_pred[BB * UU * HH];
__device__ __half g_wout[VV * HH];      // fp16 copy of W_out, [v][h]

// ---------------------------------------------------------------------------
// Fused prep kernel: blocks [0,128) enc proj, [128,192) pred proj,
// [192,256) W_out fp32->fp16 convert. Projections: BM=BN=64, BK=16 fp32.
// ---------------------------------------------------------------------------
__device__ __forceinline__ void proj_body(const float* __restrict__ X,
                                          const float* __restrict__ W,
                                          const float* __restrict__ bias,
                                          float* __restrict__ C,
                                          int m0, int n0, int N, int K,
                                          float Xs[16][65], float Ws[16][65])
{
    const int tid = threadIdx.x;
    const int ty = tid >> 4, tx = tid & 15;

    float acc[4][4];
    #pragma unroll
    for (int i = 0; i < 4; i++)
        #pragma unroll
        for (int j = 0; j < 4; j++) acc[i][j] = 0.f;

    for (int k0 = 0; k0 < K; k0 += 16) {
        #pragma unroll
        for (int i = tid; i < 1024; i += 256) {
            int r = i >> 4, c = i & 15;
            Xs[c][r] = X[(size_t)(m0 + r) * K + k0 + c];
            Ws[c][r] = W[(size_t)(n0 + r) * K + k0 + c];
        }
        __syncthreads();
        #pragma unroll
        for (int kk = 0; kk < 16; kk++) {
            float a[4], b[4];
            #pragma unroll
            for (int i = 0; i < 4; i++) a[i] = Xs[kk][ty * 4 + i];
            #pragma unroll
            for (int j = 0; j < 4; j++) b[j] = Ws[kk][tx * 4 + j];
            #pragma unroll
            for (int i = 0; i < 4; i++)
                #pragma unroll
                for (int j = 0; j < 4; j++) acc[i][j] = fmaf(a[i], b[j], acc[i][j]);
        }
        __syncthreads();
    }
    #pragma unroll
    for (int i = 0; i < 4; i++)
        #pragma unroll
        for (int j = 0; j < 4; j++) {
            int m = m0 + ty * 4 + i, n = n0 + tx * 4 + j;
            C[(size_t)m * N + n] = acc[i][j] + bias[n];
        }
}

__global__ void __launch_bounds__(256)
prep_kernel(const float* __restrict__ enc_in, const float* __restrict__ pred_in,
            const float* __restrict__ W_enc, const float* __restrict__ b_enc,
            const float* __restrict__ W_pred, const float* __restrict__ b_pred,
            const float* __restrict__ W_out,
            float* __restrict__ enc_out, float* __restrict__ pred_out)
{
    __shared__ float Xs[16][65];
    __shared__ float Ws[16][65];
    const int blk = blockIdx.x;
    if (blk < 128) {
        proj_body(enc_in, W_enc, b_enc, enc_out,
                  (blk >> 3) * 64, (blk & 7) * 64, HH, D_ENC, Xs, Ws);
    } else if (blk < 192) {
        const int t = blk - 128;
        proj_body(pred_in, W_pred, b_pred, pred_out,
                  (t >> 3) * 64, (t & 7) * 64, HH, D_PRED, Xs, Ws);
    } else {
        const int t = blk - 192;
        const int tid = threadIdx.x;
        #pragma unroll
        for (int j = 0; j < 8; j++) {
            int idx = t * 8192 + j * 1024 + tid * 4;
            float4 v = *reinterpret_cast<const float4*>(W_out + idx);
            __half2 h01 = __floats2half2_rn(v.x, v.y);
            __half2 h23 = __floats2half2_rn(v.z, v.w);
            uint2 pk;
            pk.x = *reinterpret_cast<uint32_t*>(&h01);
            pk.y = *reinterpret_cast<uint32_t*>(&h23);
            *reinterpret_cast<uint2*>(&g_wout[idx]) = pk;
        }
    }
}

// ---------------------------------------------------------------------------
// mma.sync helpers
// ---------------------------------------------------------------------------
__device__ __forceinline__ uint32_t smem_u32(const void* p) {
    return (uint32_t)__cvta_generic_to_shared(p);
}
__device__ __forceinline__ void ldmX4(uint32_t a[4], uint32_t addr) {
    asm volatile("ldmatrix.sync.aligned.m8n8.x4.shared.b16 {%0,%1,%2,%3}, [%4];"
                 : "=r"(a[0]), "=r"(a[1]), "=r"(a[2]), "=r"(a[3]) : "r"(addr));
}
__device__ __forceinline__ void mma16816(float c[4], const uint32_t a[4],
                                         uint32_t b0, uint32_t b1) {
    asm volatile(
        "mma.sync.aligned.m16n8k16.row.col.f32.f16.f16.f32 "
        "{%0,%1,%2,%3}, {%4,%5,%6,%7}, {%8,%9}, {%0,%1,%2,%3};"
        : "+f"(c[0]), "+f"(c[1]), "+f"(c[2]), "+f"(c[3])
        : "r"(a[0]), "r"(a[1]), "r"(a[2]), "r"(a[3]), "r"(b0), "r"(b1));
}
__device__ __forceinline__ void cp16(uint32_t dst, const void* src) {
    asm volatile("cp.async.cg.shared.global [%0], [%1], 16;" :: "r"(dst), "l"(src));
}

// ---------------------------------------------------------------------------
// joint kernel: BM=64, 256 threads, 2 CTAs/SM.
// A: XOR-swizzled fp16 [64][512] (64 KB). B: 3-stage cp.async pipeline,
// 3 x 16 KB chunks (256 n-rows x 32 k). Flat 64-chunk loop, epilogue at
// 16-chunk (n-tile) boundaries, prefetch crosses boundaries.
// ---------------------------------------------------------------------------
#define A_BYTES   65536
#define B_CHUNK   16384
#define OFF_A     0
#define OFF_B     A_BYTES
#define SMEM_TOTAL (A_BYTES + 3 * B_CHUNK)   // 114688

__global__ void __launch_bounds__(256, 2)
joint_kernel(const float* __restrict__ gamma, const float* __restrict__ beta,
             const float* __restrict__ b_out, float* __restrict__ out)
{
    extern __shared__ __align__(1024) char smem[];
    const uint32_t smemU = smem_u32(smem);
    const uint32_t Bs_u  = smemU + OFF_B;

    const int bt   = blockIdx.x >> 1;
    const int half = blockIdx.x & 1;
    const int bb   = bt >> 8;
    const int tid  = threadIdx.x;
    const int w    = tid >> 5, lane = tid & 31;

    // stage enc/gamma/beta in buf2 region (overwritten later by B chunk g=2)
    float* encS   = (float*)(smem + OFF_B + 2 * B_CHUNK);
    float* gammaS = encS + 512;
    float* betaS  = gammaS + 512;

    // B load lane mapping: 4 cp16 per thread per chunk
    const int nrL  = tid >> 2;          // n-row 0..63 step over p
    const int segL = tid & 3;

    // ---- issue B chunk 0 and 1 loads immediately (overlap with phase 1) ----
    {
        #pragma unroll
        for (int p = 0; p < 4; p++) {
            int nr = nrL + (p << 6);
            uint32_t dst = (uint32_t)(nr * 64 + ((segL ^ ((nr >> 1) & 3)) << 4));
            cp16(Bs_u + dst, g_wout + (size_t)nr * HH + (segL << 3));
        }
        asm volatile("cp.async.commit_group;");
        #pragma unroll
        for (int p = 0; p < 4; p++) {
            int nr = nrL + (p << 6);
            uint32_t dst = (uint32_t)(nr * 64 + ((segL ^ ((nr >> 1) & 3)) << 4));
            cp16(Bs_u + B_CHUNK + dst, g_wout + (size_t)nr * HH + 32 + (segL << 3));
        }
        asm volatile("cp.async.commit_group;");
    }

    // stage enc/gamma/beta (plain loads; small)
    for (int i = tid; i < 512; i += 256) {
        encS[i]   = g_enc[(size_t)bt * HH + i];
        gammaS[i] = gamma[i];
        betaS[i]  = beta[i];
    }
    __syncthreads();

    // ---- Phase 1: A = LN(relu(enc+pred)), fp16, XOR-swizzled rows ----
    #pragma unroll
    for (int r = 0; r < 8; r++) {
        const int u  = r * 8 + w;                  // local row 0..63
        const int ug = half * 64 + u;
        const float* pr = g_pred + ((size_t)(bb * UU + ug)) * HH;
        float v[16];
        float s = 0.f, s2 = 0.f;
        #pragma unroll
        for (int i = 0; i < 16; i++) {
            int h = lane + (i << 5);
            float x = encS[h] + pr[h];
            x = fmaxf(x, 0.f);
            v[i] = x; s += x; s2 += x * x;
        }
        #pragma unroll
        for (int o = 16; o; o >>= 1) {
            s  += __shfl_xor_sync(0xffffffffu, s,  o);
            s2 += __shfl_xor_sync(0xffffffffu, s2, o);
        }
        float mean = s * (1.f / 512.f);
        float var  = fmaxf(s2 * (1.f / 512.f) - mean * mean, 0.f);
        float rstd = rsqrtf(var + EPSV);
        const uint32_t xr = (uint32_t)((u & 7) << 4);
        #pragma unroll
        for (int i = 0; i < 16; i++) {
            int h = lane + (i << 5);
            uint32_t off = (uint32_t)(u * 1024) + ((uint32_t)((h >> 3) << 4) ^ xr)
                         + (uint32_t)((h & 7) << 1);
            *(__half*)(smem + OFF_A + off) =
                __float2half((v[i] - mean) * rstd * gammaS[h] + betaS[h]);
        }
    }
    // NOTE: no explicit barrier here; the first loop-iteration barrier covers A.

    // ---- Phase 2: GEMM 64x1024x512, flat 64-chunk pipeline ----
    const int warpM = w & 1;
    const int warpN = w >> 1;

    const int rowA0 = warpM * 32 + (lane & 15);
    const uint32_t aBase = smemU + OFF_A + (uint32_t)(rowA0 * 1024);
    const uint32_t xorA  = (uint32_t)((rowA0 & 7) << 4);
    const uint32_t klane = (uint32_t)((lane >> 4) << 4);   // +16B for k+8 lanes

    const int nLaneRow = (lane & 7) + ((lane >> 4) << 3);
    const int khalf    = (lane >> 3) & 1;
    uint32_t bBase[4], bXor[4];
    #pragma unroll
    for (int j = 0; j < 4; j++) {
        const int n = warpN * 64 + j * 16 + nLaneRow;
        bBase[j] = (uint32_t)(n * 64);
        bXor[j]  = (uint32_t)(((n >> 1) & 3) << 4);
    }

    float acc[2][8][4];
    #pragma unroll
    for (int mi = 0; mi < 2; mi++)
        #pragma unroll
        for (int ni = 0; ni < 8; ni++)
            #pragma unroll
            for (int q = 0; q < 4; q++) acc[mi][ni][q] = 0.f;

    const size_t outBase = (size_t)bt * (UU * VV) + (size_t)half * 64 * VV;

    int bufc = 0;   // buffer of current chunk g
    #pragma unroll 1
    for (int g = 0; g < 64; g++) {
        if (g < 62) {
            asm volatile("cp.async.wait_group 1;" ::: "memory");
        } else {
            asm volatile("cp.async.wait_group 0;" ::: "memory");
        }
        __syncthreads();

        // issue loads for chunk g+2
        if (g < 62) {
            const int gl = g + 2;
            const int n0l = (gl >> 4) << 8;
            const int kl  = (gl & 15) << 5;
            int bufl = bufc + 2; if (bufl >= 3) bufl -= 3;
            const uint32_t dstBase = Bs_u + (uint32_t)(bufl * B_CHUNK);
            #pragma unroll
            for (int p = 0; p < 4; p++) {
                int nr = nrL + (p << 6);
                uint32_t dst = (uint32_t)(nr * 64 + ((segL ^ ((nr >> 1) & 3)) << 4));
                cp16(dstBase + dst, g_wout + (size_t)(n0l + nr) * HH + kl + (segL << 3));
            }
            asm volatile("cp.async.commit_group;");
        }

        // compute chunk g
        const int kglob = (g & 15) << 5;
        const uint32_t bufB = Bs_u + (uint32_t)(bufc * B_CHUNK);
        #pragma unroll
        for (int kk2 = 0; kk2 < 2; kk2++) {
            const int kk = kk2 << 4;
            const uint32_t aOff = (((uint32_t)((kglob + kk) << 1) + klane) ^ xorA);
            uint32_t a[2][4];
            ldmX4(a[0], aBase + aOff);
            ldmX4(a[1], aBase + 16384u + aOff);
            const uint32_t seg16 = (uint32_t)((kk2 << 1) + khalf) << 4;
            uint32_t bf[4][4];
            #pragma unroll
            for (int j = 0; j < 4; j++)
                ldmX4(bf[j], bufB + bBase[j] + (seg16 ^ bXor[j]));
            #pragma unroll
            for (int mi = 0; mi < 2; mi++)
                #pragma unroll
                for (int ni = 0; ni < 8; ni++)
                    mma16816(acc[mi][ni], a[mi],
                             bf[ni >> 1][(ni & 1) * 2],
                             bf[ni >> 1][(ni & 1) * 2 + 1]);
        }
        if (++bufc == 3) bufc = 0;

        // epilogue at n-tile boundary (overlaps in-flight loads of next tile)
        if ((g & 15) == 15) {
            const int n0 = (g >> 4) << 8;
            #pragma unroll
            for (int mi = 0; mi < 2; mi++) {
                const int row = warpM * 32 + mi * 16 + (lane >> 2);
                #pragma unroll
                for (int ni = 0; ni < 8; ni++) {
                    const int col = n0 + warpN * 64 + ni * 8 + ((lane & 3) << 1);
                    const float2 bo = __ldg(reinterpret_cast<const float2*>(b_out + col));
                    float2 v0 = make_float2(acc[mi][ni][0] + bo.x, acc[mi][ni][1] + bo.y);
                    float2 v1 = make_float2(acc[mi][ni][2] + bo.x, acc[mi][ni][3] + bo.y);
                    *reinterpret_cast<float2*>(out + outBase + (size_t)row * VV + col)       = v0;
                    *reinterpret_cast<float2*>(out + outBase + (size_t)(row + 8) * VV + col) = v1;
                    #pragma unroll
                    for (int q = 0; q < 4; q++) acc[mi][ni][q] = 0.f;
                }
            }
        }
    }
}

// ---------------------------------------------------------------------------
extern "C" void kernel_launch(void* const* d_in, const int* in_sizes, int n_in,
                              void* d_out, int out_size)
{
    (void)in_sizes; (void)n_in; (void)out_size;
    const float* enc_in  = (const float*)d_in[0];
    const float* pred_in = (const float*)d_in[1];
    const float* W_enc   = (const float*)d_in[2];
    const float* b_enc   = (const float*)d_in[3];
    const float* W_pred  = (const float*)d_in[4];
    const float* b_pred  = (const float*)d_in[5];
    const float* gamma   = (const float*)d_in[6];
    const float* beta    = (const float*)d_in[7];
    const float* W_out   = (const float*)d_in[8];
    const float* b_out   = (const float*)d_in[9];
    float* out = (float*)d_out;

    float* enc_ptr = nullptr;
    float* pred_ptr = nullptr;
    cudaGetSymbolAddress((void**)&enc_ptr,  g_enc);
    cudaGetSymbolAddress((void**)&pred_ptr, g_pred);

    prep_kernel<<<256, 256>>>(enc_in, pred_in, W_enc, b_enc, W_pred, b_pred,
                              W_out, enc_ptr, pred_ptr);

    cudaFuncSetAttribute(joint_kernel, cudaFuncAttributeMaxDynamicSharedMemorySize,
                         SMEM_TOTAL);
    joint_kernel<<<BB * TT * 2, 256, SMEM_TOTAL>>>(gamma, beta, b_out, out);
}

// round 6
// speedup vs baseline: 1.6074x; 1.0585x over previous
#include <cuda_runtime.h>
#include <cuda_fp16.h>
#include <cuda_bf16.h>
#include <cstdint>

#define BB 4
#define TT 256
#define UU 128
#define D_ENC 512
#define D_PRED 640
#define HH 512
#define VV 1024
#define EPSV 1e-5f

// Device scratch
__device__ float  g_enc [BB * TT * HH];
__device__ float  g_pred[BB * UU * HH];
__device__ __half g_wout[VV * HH];      // fp16 copy of W_out, [v][h]

// ---------------------------------------------------------------------------
// Fused prep kernel: blocks [0,128) enc proj, [128,192) pred proj,
// [192,256) W_out fp32->fp16 convert. Projections: BM=BN=64, BK=16 fp32.
// ---------------------------------------------------------------------------
__device__ __forceinline__ void proj_body(const float* __restrict__ X,
                                          const float* __restrict__ W,
                                          const float* __restrict__ bias,
                                          float* __restrict__ C,
                                          int m0, int n0, int N, int K,
                                          float Xs[16][65], float Ws[16][65])
{
    const int tid = threadIdx.x;
    const int ty = tid >> 4, tx = tid & 15;

    float acc[4][4];
    #pragma unroll
    for (int i = 0; i < 4; i++)
        #pragma unroll
        for (int j = 0; j < 4; j++) acc[i][j] = 0.f;

    for (int k0 = 0; k0 < K; k0 += 16) {
        #pragma unroll
        for (int i = tid; i < 1024; i += 256) {
            int r = i >> 4, c = i & 15;
            Xs[c][r] = X[(size_t)(m0 + r) * K + k0 + c];
            Ws[c][r] = W[(size_t)(n0 + r) * K + k0 + c];
        }
        __syncthreads();
        #pragma unroll
        for (int kk = 0; kk < 16; kk++) {
            float a[4], b[4];
            #pragma unroll
            for (int i = 0; i < 4; i++) a[i] = Xs[kk][ty * 4 + i];
            #pragma unroll
            for (int j = 0; j < 4; j++) b[j] = Ws[kk][tx * 4 + j];
            #pragma unroll
            for (int i = 0; i < 4; i++)
                #pragma unroll
                for (int j = 0; j < 4; j++) acc[i][j] = fmaf(a[i], b[j], acc[i][j]);
        }
        __syncthreads();
    }
    #pragma unroll
    for (int i = 0; i < 4; i++)
        #pragma unroll
        for (int j = 0; j < 4; j++) {
            int m = m0 + ty * 4 + i, n = n0 + tx * 4 + j;
            C[(size_t)m * N + n] = acc[i][j] + bias[n];
        }
}

__global__ void __launch_bounds__(256)
prep_kernel(const float* __restrict__ enc_in, const float* __restrict__ pred_in,
            const float* __restrict__ W_enc, const float* __restrict__ b_enc,
            const float* __restrict__ W_pred, const float* __restrict__ b_pred,
            const float* __restrict__ W_out,
            float* __restrict__ enc_out, float* __restrict__ pred_out)
{
    __shared__ float Xs[16][65];
    __shared__ float Ws[16][65];
    const int blk = blockIdx.x;
    if (blk < 128) {
        proj_body(enc_in, W_enc, b_enc, enc_out,
                  (blk >> 3) * 64, (blk & 7) * 64, HH, D_ENC, Xs, Ws);
    } else if (blk < 192) {
        const int t = blk - 128;
        proj_body(pred_in, W_pred, b_pred, pred_out,
                  (t >> 3) * 64, (t & 7) * 64, HH, D_PRED, Xs, Ws);
    } else {
        const int t = blk - 192;
        const int tid = threadIdx.x;
        #pragma unroll
        for (int j = 0; j < 8; j++) {
            int idx = t * 8192 + j * 1024 + tid * 4;
            float4 v = *reinterpret_cast<const float4*>(W_out + idx);
            __half2 h01 = __floats2half2_rn(v.x, v.y);
            __half2 h23 = __floats2half2_rn(v.z, v.w);
            uint2 pk;
            pk.x = *reinterpret_cast<uint32_t*>(&h01);
            pk.y = *reinterpret_cast<uint32_t*>(&h23);
            *reinterpret_cast<uint2*>(&g_wout[idx]) = pk;
        }
    }
}

// ---------------------------------------------------------------------------
// mma.sync helpers
// ---------------------------------------------------------------------------
__device__ __forceinline__ uint32_t smem_u32(const void* p) {
    return (uint32_t)__cvta_generic_to_shared(p);
}
__device__ __forceinline__ void ldmX4(uint32_t a[4], uint32_t addr) {
    asm volatile("ldmatrix.sync.aligned.m8n8.x4.shared.b16 {%0,%1,%2,%3}, [%4];"
                 : "=r"(a[0]), "=r"(a[1]), "=r"(a[2]), "=r"(a[3]) : "r"(addr));
}
__device__ __forceinline__ void mma16816(float c[4], const uint32_t a[4],
                                         uint32_t b0, uint32_t b1) {
    asm volatile(
        "mma.sync.aligned.m16n8k16.row.col.f32.f16.f16.f32 "
        "{%0,%1,%2,%3}, {%4,%5,%6,%7}, {%8,%9}, {%0,%1,%2,%3};"
        : "+f"(c[0]), "+f"(c[1]), "+f"(c[2]), "+f"(c[3])
        : "r"(a[0]), "r"(a[1]), "r"(a[2]), "r"(a[3]), "r"(b0), "r"(b1));
}
__device__ __forceinline__ void cp16(uint32_t dst, const void* src) {
    asm volatile("cp.async.cg.shared.global [%0], [%1], 16;" :: "r"(dst), "l"(src));
}

// ---------------------------------------------------------------------------
// joint kernel: BM=64, 256 threads, 2 CTAs/SM. R4 nested structure.
// A: XOR-swizzled fp16 [64][512] (64 KB). B: 2 x 16 KB double buffer,
// chunk-0 load issued before phase 1 (overlaps LN).
// ---------------------------------------------------------------------------
#define A_BYTES   65536
#define B_CHUNK   16384
#define OFF_A     0
#define OFF_B     A_BYTES
#define SMEM_TOTAL (A_BYTES + 2 * B_CHUNK)   // 98304

__global__ void __launch_bounds__(256, 2)
joint_kernel(const float* __restrict__ gamma, const float* __restrict__ beta,
             const float* __restrict__ b_out, float* __restrict__ out)
{
    extern __shared__ __align__(1024) char smem[];
    const uint32_t smemU = smem_u32(smem);
    const uint32_t Bs_u  = smemU + OFF_B;

    const int bt   = blockIdx.x >> 1;
    const int half = blockIdx.x & 1;
    const int bb   = bt >> 8;
    const int tid  = threadIdx.x;
    const int w    = tid >> 5, lane = tid & 31;

    // stage enc/gamma/beta in buf1 region (overwritten later by B chunk kc=1)
    float* encS   = (float*)(smem + OFF_B + B_CHUNK);
    float* gammaS = encS + 512;
    float* betaS  = gammaS + 512;

    // B load lane mapping: 4 cp16 per thread per chunk
    const int nrL  = tid >> 2;
    const int segL = tid & 3;

    // ---- issue B chunk 0 (tile 0) load now; overlaps phase 1 compute ----
    #pragma unroll
    for (int p = 0; p < 4; p++) {
        int nr = nrL + (p << 6);
        uint32_t dst = (uint32_t)(nr * 64 + ((segL ^ ((nr >> 1) & 3)) << 4));
        cp16(Bs_u + dst, g_wout + (size_t)nr * HH + (segL << 3));
    }
    asm volatile("cp.async.commit_group;");

    for (int i = tid; i < 512; i += 256) {
        encS[i]   = g_enc[(size_t)bt * HH + i];
        gammaS[i] = gamma[i];
        betaS[i]  = beta[i];
    }
    __syncthreads();

    // ---- Phase 1: A = LN(relu(enc+pred)), fp16, XOR-swizzled rows ----
    #pragma unroll
    for (int r = 0; r < 8; r++) {
        const int u  = r * 8 + w;
        const int ug = half * 64 + u;
        const float* pr = g_pred + ((size_t)(bb * UU + ug)) * HH;
        float v[16];
        float s = 0.f, s2 = 0.f;
        #pragma unroll
        for (int i = 0; i < 16; i++) {
            int h = lane + (i << 5);
            float x = encS[h] + pr[h];
            x = fmaxf(x, 0.f);
            v[i] = x; s += x; s2 += x * x;
        }
        #pragma unroll
        for (int o = 16; o; o >>= 1) {
            s  += __shfl_xor_sync(0xffffffffu, s,  o);
            s2 += __shfl_xor_sync(0xffffffffu, s2, o);
        }
        float mean = s * (1.f / 512.f);
        float var  = fmaxf(s2 * (1.f / 512.f) - mean * mean, 0.f);
        float rstd = rsqrtf(var + EPSV);
        const uint32_t xr = (uint32_t)((u & 7) << 4);
        #pragma unroll
        for (int i = 0; i < 16; i++) {
            int h = lane + (i << 5);
            uint32_t off = (uint32_t)(u * 1024) + ((uint32_t)((h >> 3) << 4) ^ xr)
                         + (uint32_t)((h & 7) << 1);
            *(__half*)(smem + OFF_A + off) =
                __float2half((v[i] - mean) * rstd * gammaS[h] + betaS[h]);
        }
    }
    // A visibility + chunk-0 B covered by the wait+sync below.

    // ---- Phase 2: GEMM 64x1024x512, nested tiles ----
    const int warpM = w & 1;
    const int warpN = w >> 1;

    const int rowA0 = warpM * 32 + (lane & 15);
    const uint32_t aBase = smemU + OFF_A + (uint32_t)(rowA0 * 1024);
    const uint32_t xorA  = (uint32_t)((rowA0 & 7) << 4);
    const uint32_t klane = (uint32_t)((lane >> 4) << 4);

    const int nLaneRow = (lane & 7) + ((lane >> 4) << 3);
    const int khalf    = (lane >> 3) & 1;
    uint32_t bBase[4], bXor[4];
    #pragma unroll
    for (int j = 0; j < 4; j++) {
        const int n = warpN * 64 + j * 16 + nLaneRow;
        bBase[j] = (uint32_t)(n * 64);
        bXor[j]  = (uint32_t)(((n >> 1) & 3) << 4);
    }

    float acc[2][8][4];
    const size_t outBase = (size_t)bt * (UU * VV) + (size_t)half * 64 * VV;

    for (int no = 0; no < 4; no++) {
        const int n0 = no << 8;
        #pragma unroll
        for (int mi = 0; mi < 2; mi++)
            #pragma unroll
            for (int ni = 0; ni < 8; ni++)
                #pragma unroll
                for (int q = 0; q < 4; q++) acc[mi][ni][q] = 0.f;

        // chunk 0 of this tile: issued before phase 1 (no==0) or by the
        // previous tile's tail prefetch (no>0). Wait + sync.
        asm volatile("cp.async.wait_group 0;" ::: "memory");
        __syncthreads();

        for (int kc = 0; kc < 16; kc++) {
            const int buf = kc & 1;
            // prefetch next chunk (kc+1 of this tile, or chunk 0 of next tile)
            if (kc < 15 || no < 3) {
                const int kn  = (kc < 15) ? ((kc + 1) << 5) : 0;
                const int n0l = (kc < 15) ? n0 : (n0 + 256);
                const uint32_t dstBase = Bs_u + (uint32_t)((buf ^ 1) * B_CHUNK);
                #pragma unroll
                for (int p = 0; p < 4; p++) {
                    int nr = nrL + (p << 6);
                    uint32_t dst = (uint32_t)(nr * 64 + ((segL ^ ((nr >> 1) & 3)) << 4));
                    cp16(dstBase + dst, g_wout + (size_t)(n0l + nr) * HH + kn + (segL << 3));
                }
                asm volatile("cp.async.commit_group;");
            }
            const int kglob = kc << 5;
            const uint32_t bufB = Bs_u + (uint32_t)(buf * B_CHUNK);
            #pragma unroll
            for (int kk2 = 0; kk2 < 2; kk2++) {
                const int kk = kk2 << 4;
                const uint32_t aOff = (((uint32_t)((kglob + kk) << 1) + klane) ^ xorA);
                uint32_t a[2][4];
                ldmX4(a[0], aBase + aOff);
                ldmX4(a[1], aBase + 16384u + aOff);
                const uint32_t seg16 = (uint32_t)((kk2 << 1) + khalf) << 4;
                uint32_t bf[4][4];
                #pragma unroll
                for (int j = 0; j < 4; j++)
                    ldmX4(bf[j], bufB + bBase[j] + (seg16 ^ bXor[j]));
                #pragma unroll
                for (int mi = 0; mi < 2; mi++)
                    #pragma unroll
                    for (int ni = 0; ni < 8; ni++)
                        mma16816(acc[mi][ni], a[mi],
                                 bf[ni >> 1][(ni & 1) * 2],
                                 bf[ni >> 1][(ni & 1) * 2 + 1]);
            }
            if (kc < 15) {
                asm volatile("cp.async.wait_group 0;" ::: "memory");
                __syncthreads();
            }
        }

        // epilogue (overlaps next tile's chunk-0 load, which is in flight)
        #pragma unroll
        for (int mi = 0; mi < 2; mi++) {
            const int row = warpM * 32 + mi * 16 + (lane >> 2);
            #pragma unroll
            for (int ni = 0; ni < 8; ni++) {
                const int col = n0 + warpN * 64 + ni * 8 + ((lane & 3) << 1);
                const float2 bo = __ldg(reinterpret_cast<const float2*>(b_out + col));
                float2 v0 = make_float2(acc[mi][ni][0] + bo.x, acc[mi][ni][1] + bo.y);
                float2 v1 = make_float2(acc[mi][ni][2] + bo.x, acc[mi][ni][3] + bo.y);
                *reinterpret_cast<float2*>(out + outBase + (size_t)row * VV + col)       = v0;
                *reinterpret_cast<float2*>(out + outBase + (size_t)(row + 8) * VV + col) = v1;
            }
        }
    }
}

// ---------------------------------------------------------------------------
extern "C" void kernel_launch(void* const* d_in, const int* in_sizes, int n_in,
                              void* d_out, int out_size)
{
    (void)in_sizes; (void)n_in; (void)out_size;
    const float* enc_in  = (const float*)d_in[0];
    const float* pred_in = (const float*)d_in[1];
    const float* W_enc   = (const float*)d_in[2];
    const float* b_enc   = (const float*)d_in[3];
    const float* W_pred  = (const float*)d_in[4];
    const float* b_pred  = (const float*)d_in[5];
    const float* gamma   = (const float*)d_in[6];
    const float* beta    = (const float*)d_in[7];
    const float* W_out   = (const float*)d_in[8];
    const float* b_out   = (const float*)d_in[9];
    float* out = (float*)d_out;

    float* enc_ptr = nullptr;
    float* pred_ptr = nullptr;
    cudaGetSymbolAddress((void**)&enc_ptr,  g_enc);
    cudaGetSymbolAddress((void**)&pred_ptr, g_pred);

    prep_kernel<<<256, 256>>>(enc_in, pred_in, W_enc, b_enc, W_pred, b_pred,
                              W_out, enc_ptr, pred_ptr);

    cudaFuncSetAttribute(joint_kernel, cudaFuncAttributeMaxDynamicSharedMemorySize,
                         SMEM_TOTAL);
    joint_kernel<<<BB * TT * 2, 256, SMEM_TOTAL>>>(gamma, beta, b_out, out);
}